// round 3
// baseline (speedup 1.0000x reference)
#include <cuda_runtime.h>
#include <cstdint>

// y[e, o] = sum_i weight[weight_idx[e], o, i] * values[input_idx[e], i]
// E = 1M, D = 16, N_W = 1024.
//
// Strategy: counting-sort edges by weight_idx (1024 bins), then one CTA per
// weight holds the 16x16 matrix in registers and streams its edges.
// Kills the per-edge 1KB weight gather that made R1 L1tex-bound (96% L1).

#define D 16
#define NW_MAX 1024
#define PERM_CAP (1 << 21)
#define SCAN_THREADS 1024

__device__ int g_hist[NW_MAX];
__device__ int g_offsets[NW_MAX];
__device__ int g_cursor[NW_MAX];
__device__ int g_perm[PERM_CAP];

// ---------------- sort pipeline ----------------

__global__ void zero_hist_kernel(int nw) {
    int i = blockIdx.x * blockDim.x + threadIdx.x;
    if (i < nw) g_hist[i] = 0;
}

__global__ void hist_kernel(const int* __restrict__ weight_idx, int E) {
    int e = blockIdx.x * blockDim.x + threadIdx.x;
    if (e < E) atomicAdd(&g_hist[weight_idx[e]], 1);
}

// single block, exclusive scan of nw (<= 1024) bins
__global__ void scan_kernel(int nw) {
    __shared__ int s[SCAN_THREADS];
    int tid = threadIdx.x;
    int v = (tid < nw) ? g_hist[tid] : 0;
    s[tid] = v;
    __syncthreads();
    // Hillis-Steele inclusive scan
#pragma unroll
    for (int off = 1; off < SCAN_THREADS; off <<= 1) {
        int add = (tid >= off) ? s[tid - off] : 0;
        __syncthreads();
        s[tid] += add;
        __syncthreads();
    }
    int excl = s[tid] - v;
    if (tid < nw) {
        g_offsets[tid] = excl;
        g_cursor[tid]  = excl;
    }
}

__global__ void scatter_kernel(const int* __restrict__ weight_idx, int E) {
    int e = blockIdx.x * blockDim.x + threadIdx.x;
    if (e < E) {
        int w = weight_idx[e];
        int p = atomicAdd(&g_cursor[w], 1);
        g_perm[p] = e;
    }
}

// ---------------- compute: one CTA per weight ----------------

__global__ __launch_bounds__(256, 8) void compute_sorted_kernel(
    const float* __restrict__ values,    // [N_POOL, 16]
    const float4* __restrict__ weight4,  // [N_W, 64] float4
    const int* __restrict__ input_idx,   // [E]
    float* __restrict__ out)             // [E, 16]
{
    const int w     = blockIdx.x;
    const int start = g_offsets[w];
    const int count = g_hist[w];
    const int lane  = threadIdx.x & 15;   // output row o
    const int group = threadIdx.x >> 4;   // 0..15 edge slots

    // load weight row `lane` once per thread (reused for all edges)
    const float4* wr = weight4 + (size_t)w * (D * D / 4) + lane * 4;
    const float4 a = __ldg(&wr[0]);
    const float4 b = __ldg(&wr[1]);
    const float4 c = __ldg(&wr[2]);
    const float4 d = __ldg(&wr[3]);
    const float wrow[D] = {a.x, a.y, a.z, a.w,
                           b.x, b.y, b.z, b.w,
                           c.x, c.y, c.z, c.w,
                           d.x, d.y, d.z, d.w};

    // 32 edges per iteration (2 per 16-lane group, for load MLP)
    for (int base = 0; base < count; base += 32) {
        const int r0 = base + group;
        const int r1 = r0 + 16;
        const bool v0 = r0 < count;
        const bool v1 = r1 < count;

        int e0 = 0, e1 = 0;
        if (v0) e0 = __ldg(&g_perm[start + r0]);   // broadcast within group
        if (v1) e1 = __ldg(&g_perm[start + r1]);

        int i0 = 0, i1 = 0;
        if (v0) i0 = __ldg(&input_idx[e0]);
        if (v1) i1 = __ldg(&input_idx[e1]);

        float x0 = 0.f, x1 = 0.f;
        if (v0) x0 = __ldg(&values[(size_t)i0 * D + lane]);
        if (v1) x1 = __ldg(&values[(size_t)i1 * D + lane]);

        float acc0 = 0.f, acc1 = 0.f;
#pragma unroll
        for (int i = 0; i < D; i++) {
            const float b0 = __shfl_sync(0xFFFFFFFFu, x0, i, 16);
            const float b1 = __shfl_sync(0xFFFFFFFFu, x1, i, 16);
            acc0 = fmaf(wrow[i], b0, acc0);
            acc1 = fmaf(wrow[i], b1, acc1);
        }

        if (v0) out[(size_t)e0 * D + lane] = acc0;
        if (v1) out[(size_t)e1 * D + lane] = acc1;
    }
}

// ---------------- fallback (R1 kernel) for unexpected shapes ----------------

__global__ __launch_bounds__(256) void edge_linear_fallback(
    const float* __restrict__ values,
    const float4* __restrict__ weight4,
    const int* __restrict__ input_idx,
    const int* __restrict__ weight_idx,
    float* __restrict__ out, int E)
{
    const int gtid = blockIdx.x * blockDim.x + threadIdx.x;
    const int edge = gtid >> 4;
    const int lane = threadIdx.x & 15;
    if (edge >= E) return;

    const int ii = __ldg(&input_idx[edge]);
    const int wi = __ldg(&weight_idx[edge]);
    const float xl = __ldg(&values[(size_t)ii * D + lane]);

    const float4* wr = weight4 + (size_t)wi * (D * D / 4) + lane * 4;
    const float4 a = __ldg(&wr[0]);
    const float4 b = __ldg(&wr[1]);
    const float4 c = __ldg(&wr[2]);
    const float4 d = __ldg(&wr[3]);
    const float wrow[D] = {a.x, a.y, a.z, a.w,
                           b.x, b.y, b.z, b.w,
                           c.x, c.y, c.z, c.w,
                           d.x, d.y, d.z, d.w};

    float acc = 0.0f;
#pragma unroll
    for (int i = 0; i < D; i++)
        acc = fmaf(wrow[i], __shfl_sync(0xFFFFFFFFu, xl, i, 16), acc);

    out[(size_t)edge * D + lane] = acc;
}

extern "C" void kernel_launch(void* const* d_in, const int* in_sizes, int n_in,
                              void* d_out, int out_size)
{
    const float*  values     = (const float*)d_in[0];
    const float4* weight4    = (const float4*)d_in[1];
    const int*    input_idx  = (const int*)d_in[2];
    const int*    weight_idx = (const int*)d_in[3];
    float*        out        = (float*)d_out;

    const int E  = in_sizes[2];
    const int NW = in_sizes[1] / (D * D);

    if (NW > NW_MAX || E > PERM_CAP) {
        const int threads = 256;
        const long long total = (long long)E * 16;
        edge_linear_fallback<<<(int)((total + threads - 1) / threads), threads>>>(
            values, weight4, input_idx, weight_idx, out, E);
        return;
    }

    const int T = 256;
    zero_hist_kernel<<<(NW + T - 1) / T, T>>>(NW);
    hist_kernel<<<(E + T - 1) / T, T>>>(weight_idx, E);
    scan_kernel<<<1, SCAN_THREADS>>>(NW);
    scatter_kernel<<<(E + T - 1) / T, T>>>(weight_idx, E);
    compute_sorted_kernel<<<NW, T>>>(values, weight4, input_idx, out);
}

// round 4
// speedup vs baseline: 2.2028x; 2.2028x over previous
#include <cuda_runtime.h>
#include <cstdint>

// y[e, o] = sum_i weight[weight_idx[e], o, i] * values[input_idx[e], i]
// E = 1M, D = 16, N_W = 1024.
//
// R3: contention-free counting sort (per-block smem histograms + column scan +
// smem-cursor scatter; NO contended global atomics), then compute with one
// thread per edge and the weight matrix broadcast from smem (no shfl).

#define D 16
#define NW_MAX 1024
#define PERM_CAP (1 << 21)
#define B_SORT 296            // sort blocks (2 per SM)
#define T_SORT 256
#define SCAN_THREADS 1024

__device__ int g_bhist [B_SORT * NW_MAX];  // per-block histograms
__device__ int g_bstart[B_SORT * NW_MAX];  // per-block per-bin start (within bin)
__device__ int g_tot   [NW_MAX];           // per-bin totals
__device__ int g_offsets[NW_MAX];          // exclusive scan of totals
__device__ int g_perm[PERM_CAP];           // sorted edge ids
__device__ int g_pii [PERM_CAP];           // input_idx gathered alongside

// ---------------- Pass A: per-block histogram (smem atomics only) -----------

__global__ __launch_bounds__(T_SORT) void passA_hist(
    const int* __restrict__ weight_idx, int E, int chunk)
{
    __shared__ int h[NW_MAX];
    const int b = blockIdx.x;
    for (int i = threadIdx.x; i < NW_MAX; i += T_SORT) h[i] = 0;
    __syncthreads();

    const int lo = b * chunk;
    const int hi = min(lo + chunk, E);
    for (int e = lo + threadIdx.x; e < hi; e += T_SORT)
        atomicAdd(&h[weight_idx[e]], 1);
    __syncthreads();

    for (int i = threadIdx.x; i < NW_MAX; i += T_SORT)
        g_bhist[b * NW_MAX + i] = h[i];
}

// ---------------- Pass B1: column scan over blocks (per bin) ----------------

__global__ void passB1_colscan()
{
    const int w = blockIdx.x * blockDim.x + threadIdx.x;
    if (w >= NW_MAX) return;
    int run = 0;
    for (int b = 0; b < B_SORT; b++) {
        const int c = g_bhist[b * NW_MAX + w];   // coalesced across w
        g_bstart[b * NW_MAX + w] = run;
        run += c;
    }
    g_tot[w] = run;
}

// ---------------- Pass B2: exclusive scan of bin totals ---------------------

__global__ void passB2_scan()
{
    __shared__ int s[SCAN_THREADS];
    const int tid = threadIdx.x;
    const int v = g_tot[tid];
    s[tid] = v;
    __syncthreads();
#pragma unroll
    for (int off = 1; off < SCAN_THREADS; off <<= 1) {
        const int add = (tid >= off) ? s[tid - off] : 0;
        __syncthreads();
        s[tid] += add;
        __syncthreads();
    }
    g_offsets[tid] = s[tid] - v;
}

// ---------------- Pass C: scatter via pre-seeded smem cursors ---------------

__global__ __launch_bounds__(T_SORT) void passC_scatter(
    const int* __restrict__ weight_idx,
    const int* __restrict__ input_idx, int E, int chunk)
{
    __shared__ int cur[NW_MAX];
    const int b = blockIdx.x;
    for (int i = threadIdx.x; i < NW_MAX; i += T_SORT)
        cur[i] = g_offsets[i] + g_bstart[b * NW_MAX + i];
    __syncthreads();

    const int lo = b * chunk;
    const int hi = min(lo + chunk, E);
    for (int e = lo + threadIdx.x; e < hi; e += T_SORT) {
        const int w  = weight_idx[e];          // coalesced
        const int ii = input_idx[e];           // coalesced
        const int p  = atomicAdd(&cur[w], 1);  // smem only
        g_perm[p] = e;
        g_pii[p]  = ii;
    }
}

// ---------------- Compute: one CTA per weight, one thread per edge ----------

__global__ __launch_bounds__(256) void compute_sorted_kernel(
    const float* __restrict__ values,   // [N_POOL, 16]
    const float* __restrict__ weight,   // [N_W, 256]
    float* __restrict__ out)            // [E, 16]
{
    __shared__ float sW[D * D];          // this block's 16x16 matrix, row-major
    const int w = blockIdx.x;
    if (threadIdx.x < D * D)
        sW[threadIdx.x] = weight[(size_t)w * (D * D) + threadIdx.x];
    __syncthreads();

    const int start = g_offsets[w];
    const int count = g_tot[w];
    const float4* sW4 = reinterpret_cast<const float4*>(sW);

    for (int base = 0; base < count; base += 256) {
        const int r = base + threadIdx.x;
        if (r >= count) break;

        const int e  = g_perm[start + r];  // coalesced
        const int ii = g_pii [start + r];  // coalesced

        // gather x (64B)
        const float4* xp = reinterpret_cast<const float4*>(values + (size_t)ii * D);
        const float4 x0 = __ldg(&xp[0]);
        const float4 x1 = __ldg(&xp[1]);
        const float4 x2 = __ldg(&xp[2]);
        const float4 x3 = __ldg(&xp[3]);

        float y[D];
#pragma unroll
        for (int o = 0; o < D; o++) {
            const float4 w0 = sW4[o * 4 + 0];   // broadcast LDS, conflict-free
            const float4 w1 = sW4[o * 4 + 1];
            const float4 w2 = sW4[o * 4 + 2];
            const float4 w3 = sW4[o * 4 + 3];
            float acc;
            acc = fmaf(w0.x, x0.x, w0.y * x0.y);
            acc = fmaf(w0.z, x0.z, acc); acc = fmaf(w0.w, x0.w, acc);
            acc = fmaf(w1.x, x1.x, acc); acc = fmaf(w1.y, x1.y, acc);
            acc = fmaf(w1.z, x1.z, acc); acc = fmaf(w1.w, x1.w, acc);
            acc = fmaf(w2.x, x2.x, acc); acc = fmaf(w2.y, x2.y, acc);
            acc = fmaf(w2.z, x2.z, acc); acc = fmaf(w2.w, x2.w, acc);
            acc = fmaf(w3.x, x3.x, acc); acc = fmaf(w3.y, x3.y, acc);
            acc = fmaf(w3.z, x3.z, acc); acc = fmaf(w3.w, x3.w, acc);
            y[o] = acc;
        }

        // scatter y (64B)
        float4* yp = reinterpret_cast<float4*>(out + (size_t)e * D);
        yp[0] = make_float4(y[0],  y[1],  y[2],  y[3]);
        yp[1] = make_float4(y[4],  y[5],  y[6],  y[7]);
        yp[2] = make_float4(y[8],  y[9],  y[10], y[11]);
        yp[3] = make_float4(y[12], y[13], y[14], y[15]);
    }
}

// ---------------- fallback (R1 kernel) for unexpected shapes ----------------

__global__ __launch_bounds__(256) void edge_linear_fallback(
    const float* __restrict__ values,
    const float4* __restrict__ weight4,
    const int* __restrict__ input_idx,
    const int* __restrict__ weight_idx,
    float* __restrict__ out, int E)
{
    const int gtid = blockIdx.x * blockDim.x + threadIdx.x;
    const int edge = gtid >> 4;
    const int lane = threadIdx.x & 15;
    if (edge >= E) return;

    const int ii = __ldg(&input_idx[edge]);
    const int wi = __ldg(&weight_idx[edge]);
    const float xl = __ldg(&values[(size_t)ii * D + lane]);

    const float4* wr = weight4 + (size_t)wi * (D * D / 4) + lane * 4;
    const float4 a = __ldg(&wr[0]);
    const float4 b = __ldg(&wr[1]);
    const float4 c = __ldg(&wr[2]);
    const float4 d = __ldg(&wr[3]);
    const float wrow[D] = {a.x, a.y, a.z, a.w,
                           b.x, b.y, b.z, b.w,
                           c.x, c.y, c.z, c.w,
                           d.x, d.y, d.z, d.w};

    float acc = 0.0f;
#pragma unroll
    for (int i = 0; i < D; i++)
        acc = fmaf(wrow[i], __shfl_sync(0xFFFFFFFFu, xl, i, 16), acc);

    out[(size_t)edge * D + lane] = acc;
}

extern "C" void kernel_launch(void* const* d_in, const int* in_sizes, int n_in,
                              void* d_out, int out_size)
{
    const float* values     = (const float*)d_in[0];
    const float* weight     = (const float*)d_in[1];
    const int*   input_idx  = (const int*)d_in[2];
    const int*   weight_idx = (const int*)d_in[3];
    float*       out        = (float*)d_out;

    const int E  = in_sizes[2];
    const int NW = in_sizes[1] / (D * D);

    if (NW != NW_MAX || E > PERM_CAP) {
        const int threads = 256;
        const long long total = (long long)E * 16;
        edge_linear_fallback<<<(int)((total + threads - 1) / threads), threads>>>(
            values, (const float4*)weight, input_idx, weight_idx, out, E);
        return;
    }

    const int chunk = (E + B_SORT - 1) / B_SORT;

    passA_hist   <<<B_SORT, T_SORT>>>(weight_idx, E, chunk);
    passB1_colscan<<<(NW_MAX + 255) / 256, 256>>>();
    passB2_scan  <<<1, SCAN_THREADS>>>();
    passC_scatter<<<B_SORT, T_SORT>>>(weight_idx, input_idx, E, chunk);
    compute_sorted_kernel<<<NW_MAX, 256>>>(values, weight, out);
}